// round 7
// baseline (speedup 1.0000x reference)
#include <cuda_runtime.h>
#include <cuda_bf16.h>
#include <cuda_fp16.h>
#include <math.h>
#include <cstdint>

#define NN 50000
#define EE 800000
#define HH 128
#define GG 128
#define CC 10
#define SCAN_BLK 49   // ceil(50000/1024)

// ---------------- static device scratch ----------------
__device__ int   g_deg[NN];
__device__ int   g_starts[NN + 1];
__device__ int   g_part[SCAN_BLK];
__device__ int   g_cursor[NN];
__device__ int   g_src[EE];
__device__ float g_dinv[NN];
__device__ __half g_xh[(size_t)NN * HH];        // fp16 copy of x for gather
__device__ __half g_hq[(size_t)NN * HH];        // fp16 hq (GEMM out for conv2/3)
__device__ float g_bufB[(size_t)NN * HH];       // fp32 h3 for pooling
__device__ __nv_bfloat16 g_aH[(size_t)NN * HH]; // split-bf16 pair A (agg, then h2)
__device__ __nv_bfloat16 g_aL[(size_t)NN * HH];
__device__ __nv_bfloat16 g_bH[(size_t)NN * HH]; // split-bf16 pair B (h1)
__device__ __nv_bfloat16 g_bL[(size_t)NN * HH];
__device__ __nv_bfloat16 g_WcH[4 * HH * HH];    // pre-converted weights hi/lo
__device__ __nv_bfloat16 g_WcL[4 * HH * HH];
__device__ float g_pool[GG * HH];
__device__ float g_cnt[GG];

// ---------------- zero / preprocessing ----------------
__global__ void k_zero() {
    int i = blockIdx.x * blockDim.x + threadIdx.x;
    if (i < NN) g_deg[i] = 0;
    if (i < GG * HH) g_pool[i] = 0.f;
    if (i < GG) g_cnt[i] = 0.f;
}
__global__ void k_deg(const int* __restrict__ col) {
    int e = blockIdx.x * blockDim.x + threadIdx.x;
    if (e < EE) atomicAdd(&g_deg[col[e]], 1);
}

// ---- multi-block exclusive scan of g_deg -> g_starts ----
__global__ void k_part() {
    __shared__ int warp_sums[32];
    int tid = threadIdx.x;
    int lane = tid & 31, wid = tid >> 5;
    int i = blockIdx.x * 1024 + tid;
    int v = (i < NN) ? g_deg[i] : 0;
    int s = v;
    #pragma unroll
    for (int o = 1; o < 32; o <<= 1) {
        int t = __shfl_up_sync(0xFFFFFFFFu, s, o);
        if (lane >= o) s += t;
    }
    if (lane == 31) warp_sums[wid] = s;
    __syncthreads();
    if (wid == 0) {
        int ws = warp_sums[lane];
        #pragma unroll
        for (int o = 1; o < 32; o <<= 1) {
            int t = __shfl_up_sync(0xFFFFFFFFu, ws, o);
            if (lane >= o) ws += t;
        }
        warp_sums[lane] = ws;
    }
    __syncthreads();
    int offset = (wid > 0) ? warp_sums[wid - 1] : 0;
    if (i < NN) g_starts[i] = offset + s - v;
    if (tid == 1023) g_part[blockIdx.x] = offset + s;
}
__global__ void k_scanpart() {
    __shared__ int buf[64];
    int t = threadIdx.x;
    buf[t] = (t < SCAN_BLK) ? g_part[t] : 0;
    __syncthreads();
    #pragma unroll
    for (int o = 1; o < 64; o <<= 1) {
        int v = (t >= o) ? buf[t - o] : 0;
        __syncthreads();
        buf[t] += v;
        __syncthreads();
    }
    if (t < SCAN_BLK) g_part[t] = (t > 0) ? buf[t - 1] : 0;
    if (t == 0) g_starts[NN] = buf[SCAN_BLK - 1];
}
__global__ void k_addoff() {
    int i = blockIdx.x * 1024 + threadIdx.x;
    if (i < NN) g_starts[i] += g_part[blockIdx.x];
}

__global__ void k_dinv_cnt(const int* __restrict__ batch) {
    int i = blockIdx.x * blockDim.x + threadIdx.x;
    if (i < NN) {
        g_dinv[i] = rsqrtf((float)(g_deg[i] + 1));
        g_cursor[i] = g_starts[i];
        atomicAdd(&g_cnt[batch[i]], 1.f);
    }
}
__global__ void k_fill(const int* __restrict__ row, const int* __restrict__ col) {
    int e = blockIdx.x * blockDim.x + threadIdx.x;
    if (e < EE) {
        int c = col[e];
        int p = atomicAdd(&g_cursor[c], 1);
        g_src[p] = row[e];
    }
}

// ---------------- conversions ----------------
__global__ void k_convW(const float* __restrict__ W0, const float* __restrict__ W1,
                        const float* __restrict__ W2, const float* __restrict__ W3) {
    int p = blockIdx.x * blockDim.x + threadIdx.x;
    if (p >= HH * HH) return;
    const float* Ws[4] = {W0, W1, W2, W3};
    #pragma unroll
    for (int w = 0; w < 4; w++) {
        float v = __ldg(&Ws[w][p]);
        __nv_bfloat16 h = __float2bfloat16(v);
        __nv_bfloat16 l = __float2bfloat16(v - __bfloat162float(h));
        g_WcH[w * HH * HH + p] = h;
        g_WcL[w * HH * HH + p] = l;
    }
}
// x fp32 -> fp16 (vectorized)
__global__ void k_convX(const float4* __restrict__ x4) {
    int p = blockIdx.x * blockDim.x + threadIdx.x;
    if (p >= NN * HH / 4) return;
    float4 v = __ldg(&x4[p]);
    __half2 a = __floats2half2_rn(v.x, v.y);
    __half2 b = __floats2half2_rn(v.z, v.w);
    uint2 o; o.x = *(uint32_t*)&a; o.y = *(uint32_t*)&b;
    *(uint2*)&g_xh[(size_t)p * 4] = o;
}

// ---------------- aggregation ----------------
__device__ __forceinline__ void store_split4(__nv_bfloat16* H, __nv_bfloat16* L,
                                             size_t idx, float4 v) {
    __nv_bfloat16 h0 = __float2bfloat16(v.x), h1 = __float2bfloat16(v.y);
    __nv_bfloat16 h2 = __float2bfloat16(v.z), h3 = __float2bfloat16(v.w);
    __nv_bfloat162 ha; ha.x = h0; ha.y = h1;
    __nv_bfloat162 hb; hb.x = h2; hb.y = h3;
    __nv_bfloat162 la; la.x = __float2bfloat16(v.x - __bfloat162float(h0));
    la.y = __float2bfloat16(v.y - __bfloat162float(h1));
    __nv_bfloat162 lb; lb.x = __float2bfloat16(v.z - __bfloat162float(h2));
    lb.y = __float2bfloat16(v.w - __bfloat162float(h3));
    *(__nv_bfloat162*)&H[idx] = ha;
    *(__nv_bfloat162*)&H[idx + 2] = hb;
    *(__nv_bfloat162*)&L[idx] = la;
    *(__nv_bfloat162*)&L[idx + 2] = lb;
}

__device__ __forceinline__ void acc_half4(float4& acc, uint2 u) {
    __half2 a = *(__half2*)&u.x;
    __half2 b = *(__half2*)&u.y;
    float2 fa = __half22float2(a);
    float2 fb = __half22float2(b);
    acc.x += fa.x; acc.y += fa.y; acc.z += fb.x; acc.w += fb.y;
}

// gather x (fp16) -> g_aH/g_aL split bf16
__global__ void k_agg1() {
    int node = blockIdx.x * 8 + (threadIdx.x >> 5);
    if (node >= NN) return;
    int lane = threadIdx.x & 31;
    const uint2* xh = (const uint2*)g_xh;   // 4 halfs per lane
    float4 acc = make_float4(0.f, 0.f, 0.f, 0.f);
    int s = g_starts[node], e = g_starts[node + 1];
    #pragma unroll 4
    for (int j = s; j < e; j++) {
        int u = __ldg(&g_src[j]);
        acc_half4(acc, __ldg(&xh[(size_t)u * 32 + lane]));
    }
    store_split4(g_aH, g_aL, (size_t)node * HH + lane * 4, acc);
}

// gather g_hq (fp16), self+neigh, *dinv, +bias, optional relu
__global__ void k_aggn(const float* __restrict__ bias, int relu, int out_bf) {
    int node = blockIdx.x * 8 + (threadIdx.x >> 5);
    if (node >= NN) return;
    int lane = threadIdx.x & 31;
    const uint2* hq = (const uint2*)g_hq;
    float4 acc = make_float4(0.f, 0.f, 0.f, 0.f);
    acc_half4(acc, __ldg(&hq[(size_t)node * 32 + lane]));  // self term
    int s = g_starts[node], e = g_starts[node + 1];
    #pragma unroll 4
    for (int j = s; j < e; j++) {
        int u = __ldg(&g_src[j]);
        acc_half4(acc, __ldg(&hq[(size_t)u * 32 + lane]));
    }
    float dv = g_dinv[node];
    float4 b = ((const float4*)bias)[lane];
    float4 r;
    r.x = fmaf(acc.x, dv, b.x);
    r.y = fmaf(acc.y, dv, b.y);
    r.z = fmaf(acc.z, dv, b.z);
    r.w = fmaf(acc.w, dv, b.w);
    if (relu) {
        r.x = fmaxf(r.x, 0.f); r.y = fmaxf(r.y, 0.f);
        r.z = fmaxf(r.z, 0.f); r.w = fmaxf(r.w, 0.f);
    }
    if (out_bf) {
        store_split4(g_aH, g_aL, (size_t)node * HH + lane * 4, r);
    } else {
        ((float4*)g_bufB)[(size_t)node * 32 + lane] = r;
    }
}

// ---------------- HMMA GEMM ----------------
#define FL_RELU 2
#define FL_DINV 4
#define FL_OUTBF 8
#define FL_OUTH 16
#define APITCH 136
#define GEMM_SMEM (4 * 128 * APITCH * 2)

__device__ __forceinline__ void mma16816(float* c, const uint32_t* a, uint32_t b0, uint32_t b1) {
    asm volatile("mma.sync.aligned.m16n8k16.row.col.f32.bf16.bf16.f32 "
        "{%0,%1,%2,%3}, {%4,%5,%6,%7}, {%8,%9}, {%0,%1,%2,%3};"
        : "+f"(c[0]), "+f"(c[1]), "+f"(c[2]), "+f"(c[3])
        : "r"(a[0]), "r"(a[1]), "r"(a[2]), "r"(a[3]), "r"(b0), "r"(b1));
}

__device__ __forceinline__ void load_A_pre(__nv_bfloat16* Ah, __nv_bfloat16* Al,
                                           const __nv_bfloat16* AH, const __nv_bfloat16* AL,
                                           int m0, int tid) {
    #pragma unroll 4
    for (int p = tid; p < 4096; p += 256) {
        int row = p >> 5;
        int k2 = (p & 31) * 4;
        int m = m0 + row;
        uint2 hv = make_uint2(0u, 0u), lv = make_uint2(0u, 0u);
        if (m < NN) {
            hv = __ldg((const uint2*)&AH[(size_t)m * HH + k2]);
            lv = __ldg((const uint2*)&AL[(size_t)m * HH + k2]);
        }
        *(uint2*)&Ah[row * APITCH + k2] = hv;
        *(uint2*)&Al[row * APITCH + k2] = lv;
    }
}

__device__ __forceinline__ void load_W_pre(__nv_bfloat16* Wh, __nv_bfloat16* Wl,
                                           int widx, int tid) {
    const __nv_bfloat16* WH = g_WcH + (size_t)widx * HH * HH;
    const __nv_bfloat16* WL = g_WcL + (size_t)widx * HH * HH;
    #pragma unroll 4
    for (int p = tid; p < 4096; p += 256) {
        int n = p >> 5;
        int k2 = (p & 31) * 4;
        *(uint2*)&Wh[n * APITCH + k2] = __ldg((const uint2*)&WH[n * HH + k2]);
        *(uint2*)&Wl[n * APITCH + k2] = __ldg((const uint2*)&WL[n * HH + k2]);
    }
}

__device__ __forceinline__ void load_A_conv(__nv_bfloat16* Ah, __nv_bfloat16* Al,
                                            const float* A, int m0, int tid) {
    #pragma unroll 4
    for (int p = tid; p < 8192; p += 256) {
        int row = p >> 6;
        int k2 = (p & 63) * 2;
        int m = m0 + row;
        float2 v = make_float2(0.f, 0.f);
        if (m < NN) v = __ldg((const float2*)&A[(size_t)m * HH + k2]);
        __nv_bfloat16 h0 = __float2bfloat16(v.x);
        __nv_bfloat16 h1 = __float2bfloat16(v.y);
        __nv_bfloat162 hv; hv.x = h0; hv.y = h1;
        __nv_bfloat162 lv;
        lv.x = __float2bfloat16(v.x - __bfloat162float(h0));
        lv.y = __float2bfloat16(v.y - __bfloat162float(h1));
        *(__nv_bfloat162*)&Ah[row * APITCH + k2] = hv;
        *(__nv_bfloat162*)&Al[row * APITCH + k2] = lv;
    }
}

struct Frag { float c[2][8][4]; };

__device__ __forceinline__ void mma_stage(Frag& f, const __nv_bfloat16* Ah,
                                          const __nv_bfloat16* Al,
                                          const __nv_bfloat16* Wh,
                                          const __nv_bfloat16* Wl,
                                          int wm, int wn, int lane) {
    int g = lane >> 2, tig = lane & 3;
    #pragma unroll 1
    for (int pass = 0; pass < 3; pass++) {
        const __nv_bfloat16* As = (pass == 2) ? Al : Ah;
        const __nv_bfloat16* Ws = (pass == 1) ? Wl : Wh;
        #pragma unroll
        for (int ks = 0; ks < 8; ks++) {
            int kb = ks * 16 + 2 * tig;
            uint32_t a[2][4];
            #pragma unroll
            for (int mt = 0; mt < 2; mt++) {
                int r = wm + mt * 16 + g;
                a[mt][0] = *(const uint32_t*)&As[r * APITCH + kb];
                a[mt][1] = *(const uint32_t*)&As[(r + 8) * APITCH + kb];
                a[mt][2] = *(const uint32_t*)&As[r * APITCH + kb + 8];
                a[mt][3] = *(const uint32_t*)&As[(r + 8) * APITCH + kb + 8];
            }
            #pragma unroll
            for (int nt = 0; nt < 8; nt++) {
                int n = wn + nt * 8 + g;
                uint32_t b0 = *(const uint32_t*)&Ws[n * APITCH + kb];
                uint32_t b1 = *(const uint32_t*)&Ws[n * APITCH + kb + 8];
                mma16816(f.c[0][nt], a[0], b0, b1);
                mma16816(f.c[1][nt], a[1], b0, b1);
            }
        }
    }
}

__global__ __launch_bounds__(256, 1) void k_gemm(
    const __nv_bfloat16* __restrict__ AH, const __nv_bfloat16* __restrict__ AL,
    int w0, const float* __restrict__ x2, int w1,
    const float* __restrict__ bias, int flags,
    __half* __restrict__ outHalf,
    __nv_bfloat16* __restrict__ outH, __nv_bfloat16* __restrict__ outL)
{
    extern __shared__ __nv_bfloat16 sm[];
    __nv_bfloat16* Ah = sm;
    __nv_bfloat16* Al = Ah + 128 * APITCH;
    __nv_bfloat16* Wh = Al + 128 * APITCH;
    __nv_bfloat16* Wl = Wh + 128 * APITCH;
    int tid = threadIdx.x, wid = tid >> 5, lane = tid & 31;
    int m0 = blockIdx.x * 128;
    int wm = (wid & 3) * 32;
    int wn = (wid >> 2) * 64;
    int g = lane >> 2, tig = lane & 3;

    Frag f;
    #pragma unroll
    for (int mt = 0; mt < 2; mt++)
        #pragma unroll
        for (int nt = 0; nt < 8; nt++)
            #pragma unroll
            for (int j = 0; j < 4; j++) f.c[mt][nt][j] = 0.f;

    load_A_pre(Ah, Al, AH, AL, m0, tid);
    load_W_pre(Wh, Wl, w0, tid);
    __syncthreads();
    mma_stage(f, Ah, Al, Wh, Wl, wm, wn, lane);

    if (x2) {
        __syncthreads();
        load_A_conv(Ah, Al, x2, m0, tid);
        load_W_pre(Wh, Wl, w1, tid);
        __syncthreads();
        mma_stage(f, Ah, Al, Wh, Wl, wm, wn, lane);
    }

    #pragma unroll
    for (int mt = 0; mt < 2; mt++) {
        #pragma unroll
        for (int half = 0; half < 2; half++) {
            int m = m0 + wm + mt * 16 + g + half * 8;
            if (m >= NN) continue;
            float dv = (flags & FL_DINV) ? g_dinv[m] : 1.f;
            #pragma unroll
            for (int nt = 0; nt < 8; nt++) {
                int col = wn + nt * 8 + 2 * tig;
                float vx = f.c[mt][nt][half * 2 + 0];
                float vy = f.c[mt][nt][half * 2 + 1];
                if (bias) {
                    float2 b2 = __ldg((const float2*)&bias[col]);
                    vx += b2.x; vy += b2.y;
                }
                if (flags & FL_DINV) { vx *= dv; vy *= dv; }
                if (flags & FL_RELU) { vx = fmaxf(vx, 0.f); vy = fmaxf(vy, 0.f); }
                if (flags & FL_OUTH) {
                    __half2 hv = __floats2half2_rn(vx, vy);
                    *(__half2*)&outHalf[(size_t)m * HH + col] = hv;
                } else if (flags & FL_OUTBF) {
                    __nv_bfloat16 h0 = __float2bfloat16(vx);
                    __nv_bfloat16 h1 = __float2bfloat16(vy);
                    __nv_bfloat162 hv; hv.x = h0; hv.y = h1;
                    __nv_bfloat162 lv;
                    lv.x = __float2bfloat16(vx - __bfloat162float(h0));
                    lv.y = __float2bfloat16(vy - __bfloat162float(h1));
                    *(__nv_bfloat162*)&outH[(size_t)m * HH + col] = hv;
                    *(__nv_bfloat162*)&outL[(size_t)m * HH + col] = lv;
                }
            }
        }
    }
}

// ---------------- pooling + fused finalize ----------------
__global__ void k_pool2(const int* __restrict__ batch) {
    const float* h = g_bufB;
    int c = threadIdx.x;
    int n0 = blockIdx.x * 64;
    int n1 = n0 + 64; if (n1 > NN) n1 = NN;
    if (n0 >= NN) return;
    float acc = 0.f;
    int cur = __ldg(&batch[n0]);
    for (int n = n0; n < n1; n++) {
        int b = __ldg(&batch[n]);
        if (b != cur) { atomicAdd(&g_pool[cur * HH + c], acc); acc = 0.f; cur = b; }
        acc += h[(size_t)n * HH + c];
    }
    atomicAdd(&g_pool[cur * HH + c], acc);
}

__global__ void k_final(const float* __restrict__ Wl, const float* __restrict__ bl,
                        float* __restrict__ dout) {
    __shared__ float ws[4];
    __shared__ float xs[HH];
    __shared__ float winv[CC];
    int g = blockIdx.x, t = threadIdx.x;
    float c = fmaxf(g_cnt[g], 1.f);
    float v = g_pool[g * HH + t] / c;
    float s = v * v;
    #pragma unroll
    for (int o = 16; o > 0; o >>= 1) s += __shfl_down_sync(0xFFFFFFFFu, s, o);
    if ((t & 31) == 0) ws[t >> 5] = s;
    if (t < CC) {
        float sw = 0.f;
        #pragma unroll 8
        for (int k = 0; k < HH; k++) { float w = __ldg(&Wl[t * HH + k]); sw = fmaf(w, w, sw); }
        winv[t] = 1.f / fmaxf(sqrtf(sw), 1e-12f);
    }
    __syncthreads();
    float tot = ws[0] + ws[1] + ws[2] + ws[3];
    float nrm = fmaxf(sqrtf(tot), 1e-12f);
    float xn = v / nrm;
    dout[g * HH + t] = xn;
    xs[t] = xn;
    __syncthreads();
    if (t < CC) {
        float s2 = 0.f;
        #pragma unroll 8
        for (int k = 0; k < HH; k++) s2 = fmaf(xs[k], __ldg(&Wl[t * HH + k]), s2);
        dout[GG * HH + g * CC + t] = fmaf(s2, winv[t], bl[t]);
    }
}

// ---------------- launch ----------------
extern "C" void kernel_launch(void* const* d_in, const int* in_sizes, int n_in,
                              void* d_out, int out_size) {
    const float* x    = (const float*)d_in[0];
    const int*   ei   = (const int*)d_in[1];
    const int*   batch= (const int*)d_in[2];
    const float* W1r  = (const float*)d_in[3];
    const float* b1   = (const float*)d_in[4];
    const float* W1x  = (const float*)d_in[5];
    const float* W2   = (const float*)d_in[6];
    const float* b2   = (const float*)d_in[7];
    const float* W3   = (const float*)d_in[8];
    const float* b3   = (const float*)d_in[9];
    const float* Wl   = (const float*)d_in[10];
    const float* bl   = (const float*)d_in[11];
    const int* row = ei;
    const int* col = ei + EE;
    float* out = (float*)d_out;

    cudaFuncSetAttribute(k_gemm, cudaFuncAttributeMaxDynamicSharedMemorySize, GEMM_SMEM);

    __nv_bfloat16 *aH, *aL, *bH, *bL;
    cudaGetSymbolAddress((void**)&aH, g_aH);
    cudaGetSymbolAddress((void**)&aL, g_aL);
    cudaGetSymbolAddress((void**)&bH, g_bH);
    cudaGetSymbolAddress((void**)&bL, g_bL);
    __half* hq;
    cudaGetSymbolAddress((void**)&hq, g_hq);

    // CSR build + degree norm (+ graph counts) + conversions
    k_zero<<<(NN + 255) / 256, 256>>>();
    k_deg<<<(EE + 255) / 256, 256>>>(col);
    k_convW<<<(HH * HH + 255) / 256, 256>>>(W1r, W1x, W2, W3);
    k_convX<<<(NN * HH / 4 + 255) / 256, 256>>>((const float4*)x);
    k_part<<<SCAN_BLK, 1024>>>();
    k_scanpart<<<1, 64>>>();
    k_addoff<<<SCAN_BLK, 1024>>>();
    k_dinv_cnt<<<(NN + 255) / 256, 256>>>(batch);
    k_fill<<<(EE + 255) / 256, 256>>>(row, col);

    int AGG_GRID = (NN + 7) / 8;
    int GB = (NN + 127) / 128;

    // conv1 (fused): h1 = relu(agg@W1r^T + x@W1x^T + b1) -> split bf16 (bH/bL)
    k_agg1<<<AGG_GRID, 256>>>();
    k_gemm<<<GB, 256, GEMM_SMEM>>>(aH, aL, 0, x, 1, b1, FL_RELU | FL_OUTBF,
                                   nullptr, bH, bL);

    // conv2: hq2 = (h1@W2^T)*dinv -> fp16 g_hq; h2 = relu(dinv*(sum)+b2) -> aH/aL
    k_gemm<<<GB, 256, GEMM_SMEM>>>(bH, bL, 2, nullptr, 0, nullptr, FL_DINV | FL_OUTH,
                                   hq, nullptr, nullptr);
    k_aggn<<<AGG_GRID, 256>>>(b2, 1, 1);

    // conv3: hq3 = (h2@W3^T)*dinv -> g_hq; h3 = dinv*(sum)+b3 -> fp32 bufB
    k_gemm<<<GB, 256, GEMM_SMEM>>>(aH, aL, 3, nullptr, 0, nullptr, FL_DINV | FL_OUTH,
                                   hq, nullptr, nullptr);
    k_aggn<<<AGG_GRID, 256>>>(b3, 0, 0);

    // pooling + normalize + classifier
    k_pool2<<<(NN + 63) / 64, 128>>>(batch);
    k_final<<<GG, HH>>>(Wl, bl, out);
}

// round 8
// speedup vs baseline: 1.3635x; 1.3635x over previous
#include <cuda_runtime.h>
#include <cuda_fp16.h>
#include <math.h>
#include <cstdint>

#define NN 50000
#define EE 800000
#define HH 128
#define GG 128
#define CC 10
#define SCAN_BLK 49   // ceil(50000/1024)

// ---------------- static device scratch ----------------
__device__ int   g_deg[NN];
__device__ int   g_starts[NN + 1];
__device__ int   g_part[SCAN_BLK];
__device__ int   g_cursor[NN];
__device__ int   g_src[EE];
__device__ float g_dinv[NN];
__device__ __half g_xh[(size_t)NN * HH];   // fp16 x
__device__ __half g_agg[(size_t)NN * HH];  // fp16 aggregated x
__device__ __half g_h1[(size_t)NN * HH];   // fp16 h1
__device__ __half g_h2[(size_t)NN * HH];   // fp16 h2
__device__ __half g_hq[(size_t)NN * HH];   // fp16 hq (conv2/3 GEMM out)
__device__ float g_bufB[(size_t)NN * HH];  // fp32 h3 for pooling
__device__ __half g_Wc[4 * HH * HH];       // fp16 weights
__device__ float g_pool[GG * HH];
__device__ float g_cnt[GG];

// ---------------- zero / preprocessing ----------------
__global__ void k_zero() {
    int i = blockIdx.x * blockDim.x + threadIdx.x;
    if (i < NN) g_deg[i] = 0;
    if (i < GG * HH) g_pool[i] = 0.f;
    if (i < GG) g_cnt[i] = 0.f;
}
__global__ void k_deg(const int* __restrict__ col) {
    int e = blockIdx.x * blockDim.x + threadIdx.x;
    if (e < EE) atomicAdd(&g_deg[col[e]], 1);
}

// conversions: x -> fp16, W -> fp16 (single launch)
__global__ void k_conv(const float4* __restrict__ x4,
                       const float* __restrict__ W0, const float* __restrict__ W1,
                       const float* __restrict__ W2, const float* __restrict__ W3) {
    int p = blockIdx.x * blockDim.x + threadIdx.x;
    if (p < NN * HH / 4) {
        float4 v = __ldg(&x4[p]);
        __half2 a = __floats2half2_rn(v.x, v.y);
        __half2 b = __floats2half2_rn(v.z, v.w);
        uint2 o; o.x = *(uint32_t*)&a; o.y = *(uint32_t*)&b;
        *(uint2*)&g_xh[(size_t)p * 4] = o;
    }
    if (p < HH * HH) {
        g_Wc[0 * HH * HH + p] = __float2half(__ldg(&W0[p]));
        g_Wc[1 * HH * HH + p] = __float2half(__ldg(&W1[p]));
        g_Wc[2 * HH * HH + p] = __float2half(__ldg(&W2[p]));
        g_Wc[3 * HH * HH + p] = __float2half(__ldg(&W3[p]));
    }
}

// ---- multi-block exclusive scan of g_deg -> g_starts ----
__global__ void k_part() {
    __shared__ int warp_sums[32];
    int tid = threadIdx.x;
    int lane = tid & 31, wid = tid >> 5;
    int i = blockIdx.x * 1024 + tid;
    int v = (i < NN) ? g_deg[i] : 0;
    int s = v;
    #pragma unroll
    for (int o = 1; o < 32; o <<= 1) {
        int t = __shfl_up_sync(0xFFFFFFFFu, s, o);
        if (lane >= o) s += t;
    }
    if (lane == 31) warp_sums[wid] = s;
    __syncthreads();
    if (wid == 0) {
        int ws = warp_sums[lane];
        #pragma unroll
        for (int o = 1; o < 32; o <<= 1) {
            int t = __shfl_up_sync(0xFFFFFFFFu, ws, o);
            if (lane >= o) ws += t;
        }
        warp_sums[lane] = ws;
    }
    __syncthreads();
    int offset = (wid > 0) ? warp_sums[wid - 1] : 0;
    if (i < NN) g_starts[i] = offset + s - v;
    if (tid == 1023) g_part[blockIdx.x] = offset + s;
}
__global__ void k_scanpart() {
    __shared__ int buf[64];
    int t = threadIdx.x;
    buf[t] = (t < SCAN_BLK) ? g_part[t] : 0;
    __syncthreads();
    #pragma unroll
    for (int o = 1; o < 64; o <<= 1) {
        int v = (t >= o) ? buf[t - o] : 0;
        __syncthreads();
        buf[t] += v;
        __syncthreads();
    }
    if (t < SCAN_BLK) g_part[t] = (t > 0) ? buf[t - 1] : 0;
    if (t == 0) g_starts[NN] = buf[SCAN_BLK - 1];
}
__global__ void k_addoff() {
    int i = blockIdx.x * 1024 + threadIdx.x;
    if (i < NN) g_starts[i] += g_part[blockIdx.x];
}

__global__ void k_dinv_cnt(const int* __restrict__ batch) {
    int i = blockIdx.x * blockDim.x + threadIdx.x;
    if (i < NN) {
        g_dinv[i] = rsqrtf((float)(g_deg[i] + 1));
        g_cursor[i] = g_starts[i];
        atomicAdd(&g_cnt[batch[i]], 1.f);
    }
}
__global__ void k_fill(const int* __restrict__ row, const int* __restrict__ col) {
    int e = blockIdx.x * blockDim.x + threadIdx.x;
    if (e < EE) {
        int c = col[e];
        int p = atomicAdd(&g_cursor[c], 1);
        g_src[p] = row[e];
    }
}

// ---------------- aggregation ----------------
__device__ __forceinline__ void acc_half4(float4& acc, uint2 u) {
    __half2 a = *(__half2*)&u.x;
    __half2 b = *(__half2*)&u.y;
    float2 fa = __half22float2(a);
    float2 fb = __half22float2(b);
    acc.x += fa.x; acc.y += fa.y; acc.z += fb.x; acc.w += fb.y;
}
__device__ __forceinline__ void store_half4(__half* dst, size_t idx, float4 v) {
    __half2 a = __floats2half2_rn(v.x, v.y);
    __half2 b = __floats2half2_rn(v.z, v.w);
    uint2 o; o.x = *(uint32_t*)&a; o.y = *(uint32_t*)&b;
    *(uint2*)&dst[idx] = o;
}

// gather x (fp16) -> g_agg (fp16)
__global__ void k_agg1() {
    int node = blockIdx.x * 8 + (threadIdx.x >> 5);
    if (node >= NN) return;
    int lane = threadIdx.x & 31;
    const uint2* xh = (const uint2*)g_xh;
    float4 acc = make_float4(0.f, 0.f, 0.f, 0.f);
    int s = g_starts[node], e = g_starts[node + 1];
    #pragma unroll 4
    for (int j = s; j < e; j++) {
        int u = __ldg(&g_src[j]);
        acc_half4(acc, __ldg(&xh[(size_t)u * 32 + lane]));
    }
    store_half4(g_agg, (size_t)node * HH + lane * 4, acc);
}

// gather g_hq (fp16), self+neigh, *dinv, +bias, optional relu
// mode 1: fp16 -> g_h2 ; mode 0: fp32 -> g_bufB
__global__ void k_aggn(const float* __restrict__ bias, int relu, int mode) {
    int node = blockIdx.x * 8 + (threadIdx.x >> 5);
    if (node >= NN) return;
    int lane = threadIdx.x & 31;
    const uint2* hq = (const uint2*)g_hq;
    float4 acc = make_float4(0.f, 0.f, 0.f, 0.f);
    acc_half4(acc, __ldg(&hq[(size_t)node * 32 + lane]));  // self
    int s = g_starts[node], e = g_starts[node + 1];
    #pragma unroll 4
    for (int j = s; j < e; j++) {
        int u = __ldg(&g_src[j]);
        acc_half4(acc, __ldg(&hq[(size_t)u * 32 + lane]));
    }
    float dv = g_dinv[node];
    float4 b = ((const float4*)bias)[lane];
    float4 r;
    r.x = fmaf(acc.x, dv, b.x);
    r.y = fmaf(acc.y, dv, b.y);
    r.z = fmaf(acc.z, dv, b.z);
    r.w = fmaf(acc.w, dv, b.w);
    if (relu) {
        r.x = fmaxf(r.x, 0.f); r.y = fmaxf(r.y, 0.f);
        r.z = fmaxf(r.z, 0.f); r.w = fmaxf(r.w, 0.f);
    }
    if (mode) {
        store_half4(g_h2, (size_t)node * HH + lane * 4, r);
    } else {
        ((float4*)g_bufB)[(size_t)node * 32 + lane] = r;
    }
}

// ---------------- HMMA GEMM (single-pass fp16) ----------------
#define FL_RELU 2
#define FL_DINV 4
#define APITCH 136
#define GEMM_SMEM (2 * 128 * APITCH * 2)

__device__ __forceinline__ void mma16816(float* c, const uint32_t* a, uint32_t b0, uint32_t b1) {
    asm volatile("mma.sync.aligned.m16n8k16.row.col.f32.f16.f16.f32 "
        "{%0,%1,%2,%3}, {%4,%5,%6,%7}, {%8,%9}, {%0,%1,%2,%3};"
        : "+f"(c[0]), "+f"(c[1]), "+f"(c[2]), "+f"(c[3])
        : "r"(a[0]), "r"(a[1]), "r"(a[2]), "r"(a[3]), "r"(b0), "r"(b1));
}

// copy fp16 tile [128 x 128] global -> padded smem
__device__ __forceinline__ void load_tile(__half* dst, const __half* src, int m0,
                                          int bound, int tid) {
    const uint2* s2 = (const uint2*)src;
    #pragma unroll 4
    for (int p = tid; p < 4096; p += 256) {
        int row = p >> 5;
        int c4 = (p & 31);
        int m = m0 + row;
        uint2 v = make_uint2(0u, 0u);
        if (m < bound) v = __ldg(&s2[(size_t)m * 32 + c4]);
        *(uint2*)&dst[row * APITCH + c4 * 4] = v;
    }
}

struct Frag { float c[2][8][4]; };

__device__ __forceinline__ void mma_stage(Frag& f, const __half* As, const __half* Ws,
                                          int wm, int wn, int lane) {
    int g = lane >> 2, tig = lane & 3;
    #pragma unroll
    for (int ks = 0; ks < 8; ks++) {
        int kb = ks * 16 + 2 * tig;
        uint32_t a[2][4];
        #pragma unroll
        for (int mt = 0; mt < 2; mt++) {
            int r = wm + mt * 16 + g;
            a[mt][0] = *(const uint32_t*)&As[r * APITCH + kb];
            a[mt][1] = *(const uint32_t*)&As[(r + 8) * APITCH + kb];
            a[mt][2] = *(const uint32_t*)&As[r * APITCH + kb + 8];
            a[mt][3] = *(const uint32_t*)&As[(r + 8) * APITCH + kb + 8];
        }
        #pragma unroll
        for (int nt = 0; nt < 8; nt++) {
            int n = wn + nt * 8 + g;
            uint32_t b0 = *(const uint32_t*)&Ws[n * APITCH + kb];
            uint32_t b1 = *(const uint32_t*)&Ws[n * APITCH + kb + 8];
            mma16816(f.c[0][nt], a[0], b0, b1);
            mma16816(f.c[1][nt], a[1], b0, b1);
        }
    }
}

// C[M,128] = A@W[w0]^T (+ A2@W[w1]^T) (+bias) (*dinv) (relu) -> fp16 out
__global__ __launch_bounds__(256, 2) void k_gemm(
    const __half* __restrict__ A, int w0,
    const __half* __restrict__ A2, int w1,
    const float* __restrict__ bias, int flags,
    __half* __restrict__ outp)
{
    extern __shared__ __half sm[];
    __half* Ah = sm;
    __half* Wh = Ah + 128 * APITCH;
    int tid = threadIdx.x, wid = tid >> 5, lane = tid & 31;
    int m0 = blockIdx.x * 128;
    int wm = (wid & 3) * 32;
    int wn = (wid >> 2) * 64;
    int g = lane >> 2, tig = lane & 3;

    Frag f;
    #pragma unroll
    for (int mt = 0; mt < 2; mt++)
        #pragma unroll
        for (int nt = 0; nt < 8; nt++)
            #pragma unroll
            for (int j = 0; j < 4; j++) f.c[mt][nt][j] = 0.f;

    load_tile(Ah, A, m0, NN, tid);
    load_tile(Wh, g_Wc + (size_t)w0 * HH * HH, 0, HH, tid);
    __syncthreads();
    mma_stage(f, Ah, Wh, wm, wn, lane);

    if (A2) {
        __syncthreads();
        load_tile(Ah, A2, m0, NN, tid);
        load_tile(Wh, g_Wc + (size_t)w1 * HH * HH, 0, HH, tid);
        __syncthreads();
        mma_stage(f, Ah, Wh, wm, wn, lane);
    }

    #pragma unroll
    for (int mt = 0; mt < 2; mt++) {
        #pragma unroll
        for (int half = 0; half < 2; half++) {
            int m = m0 + wm + mt * 16 + g + half * 8;
            if (m >= NN) continue;
            float dv = (flags & FL_DINV) ? g_dinv[m] : 1.f;
            #pragma unroll
            for (int nt = 0; nt < 8; nt++) {
                int col = wn + nt * 8 + 2 * tig;
                float vx = f.c[mt][nt][half * 2 + 0];
                float vy = f.c[mt][nt][half * 2 + 1];
                if (bias) {
                    float2 b2 = __ldg((const float2*)&bias[col]);
                    vx += b2.x; vy += b2.y;
                }
                if (flags & FL_DINV) { vx *= dv; vy *= dv; }
                if (flags & FL_RELU) { vx = fmaxf(vx, 0.f); vy = fmaxf(vy, 0.f); }
                __half2 hv = __floats2half2_rn(vx, vy);
                *(__half2*)&outp[(size_t)m * HH + col] = hv;
            }
        }
    }
}

// ---------------- pooling + fused finalize ----------------
__global__ void k_pool2(const int* __restrict__ batch) {
    const float* h = g_bufB;
    int c = threadIdx.x;
    int n0 = blockIdx.x * 64;
    int n1 = n0 + 64; if (n1 > NN) n1 = NN;
    if (n0 >= NN) return;
    float acc = 0.f;
    int cur = __ldg(&batch[n0]);
    for (int n = n0; n < n1; n++) {
        int b = __ldg(&batch[n]);
        if (b != cur) { atomicAdd(&g_pool[cur * HH + c], acc); acc = 0.f; cur = b; }
        acc += h[(size_t)n * HH + c];
    }
    atomicAdd(&g_pool[cur * HH + c], acc);
}

__global__ void k_final(const float* __restrict__ Wl, const float* __restrict__ bl,
                        float* __restrict__ dout) {
    __shared__ float ws[4];
    __shared__ float xs[HH];
    __shared__ float winv[CC];
    int g = blockIdx.x, t = threadIdx.x;
    float c = fmaxf(g_cnt[g], 1.f);
    float v = g_pool[g * HH + t] / c;
    float s = v * v;
    #pragma unroll
    for (int o = 16; o > 0; o >>= 1) s += __shfl_down_sync(0xFFFFFFFFu, s, o);
    if ((t & 31) == 0) ws[t >> 5] = s;
    if (t < CC) {
        float sw = 0.f;
        #pragma unroll 8
        for (int k = 0; k < HH; k++) { float w = __ldg(&Wl[t * HH + k]); sw = fmaf(w, w, sw); }
        winv[t] = 1.f / fmaxf(sqrtf(sw), 1e-12f);
    }
    __syncthreads();
    float tot = ws[0] + ws[1] + ws[2] + ws[3];
    float nrm = fmaxf(sqrtf(tot), 1e-12f);
    float xn = v / nrm;
    dout[g * HH + t] = xn;
    xs[t] = xn;
    __syncthreads();
    if (t < CC) {
        float s2 = 0.f;
        #pragma unroll 8
        for (int k = 0; k < HH; k++) s2 = fmaf(xs[k], __ldg(&Wl[t * HH + k]), s2);
        dout[GG * HH + g * CC + t] = fmaf(s2, winv[t], bl[t]);
    }
}

// ---------------- launch ----------------
extern "C" void kernel_launch(void* const* d_in, const int* in_sizes, int n_in,
                              void* d_out, int out_size) {
    const float* x    = (const float*)d_in[0];
    const int*   ei   = (const int*)d_in[1];
    const int*   batch= (const int*)d_in[2];
    const float* W1r  = (const float*)d_in[3];
    const float* b1   = (const float*)d_in[4];
    const float* W1x  = (const float*)d_in[5];
    const float* W2   = (const float*)d_in[6];
    const float* b2   = (const float*)d_in[7];
    const float* W3   = (const float*)d_in[8];
    const float* b3   = (const float*)d_in[9];
    const float* Wl   = (const float*)d_in[10];
    const float* bl   = (const float*)d_in[11];
    const int* row = ei;
    const int* col = ei + EE;
    float* out = (float*)d_out;

    cudaFuncSetAttribute(k_gemm, cudaFuncAttributeMaxDynamicSharedMemorySize, GEMM_SMEM);

    __half *xh, *agg, *h1, *h2, *hq;
    cudaGetSymbolAddress((void**)&xh, g_xh);
    cudaGetSymbolAddress((void**)&agg, g_agg);
    cudaGetSymbolAddress((void**)&h1, g_h1);
    cudaGetSymbolAddress((void**)&h2, g_h2);
    cudaGetSymbolAddress((void**)&hq, g_hq);

    // CSR build + degree norm (+ graph counts) + conversions
    k_zero<<<(NN + 255) / 256, 256>>>();
    k_deg<<<(EE + 255) / 256, 256>>>(col);
    k_conv<<<(NN * HH / 4 + 255) / 256, 256>>>((const float4*)x, W1r, W1x, W2, W3);
    k_part<<<SCAN_BLK, 1024>>>();
    k_scanpart<<<1, 64>>>();
    k_addoff<<<SCAN_BLK, 1024>>>();
    k_dinv_cnt<<<(NN + 255) / 256, 256>>>(batch);
    k_fill<<<(EE + 255) / 256, 256>>>(row, col);

    int AGG_GRID = (NN + 7) / 8;
    int GB = (NN + 127) / 128;

    // conv1 (fused): h1 = relu(agg@W1r^T + x@W1x^T + b1) -> fp16
    k_agg1<<<AGG_GRID, 256>>>();
    k_gemm<<<GB, 256, GEMM_SMEM>>>(agg, 0, xh, 1, b1, FL_RELU, h1);

    // conv2: hq2 = (h1@W2^T)*dinv -> fp16; h2 = relu(dinv*(sum)+b2) -> fp16
    k_gemm<<<GB, 256, GEMM_SMEM>>>(h1, 2, nullptr, 0, nullptr, FL_DINV, hq);
    k_aggn<<<AGG_GRID, 256>>>(b2, 1, 1);

    // conv3: hq3 = (h2@W3^T)*dinv -> fp16; h3 = dinv*(sum)+b3 -> fp32 bufB
    k_gemm<<<GB, 256, GEMM_SMEM>>>(h2, 3, nullptr, 0, nullptr, FL_DINV, hq);
    k_aggn<<<AGG_GRID, 256>>>(b3, 0, 0);

    // pooling + normalize + classifier
    k_pool2<<<(NN + 63) / 64, 128>>>(batch);
    k_final<<<GG, HH>>>(Wl, bl, out);
}